// round 15
// baseline (speedup 1.0000x reference)
#include <cuda_runtime.h>
#include <cuda_fp16.h>
#include <cstdint>

#define DI __device__ __forceinline__

// ---------------- problem dims ----------------
constexpr int Mdim = 16384;   // B*S
constexpr int Kdim = 2048;    // IN
constexpr int Ndim = 2048;    // OUT
constexpr int LR   = 128;     // L*R
constexpr int Rr   = 32;

// ---------------- scratch ----------------
__device__ uint4 g_xh_raw[(size_t)Mdim * Kdim * 2 / 16];   // fp16 x      (64 MB)
__device__ uint4 g_wh_raw[(size_t)Ndim * Kdim * 2 / 16];   // fp16 W_eff  (8 MB)

// ---------------- PTX helpers (family-portable only) ----------------
DI uint32_t smem_u32(const void* p) {
    uint32_t a;
    asm("{ .reg .u64 t; cvta.to.shared.u64 t, %1; cvt.u32.u64 %0, t; }" : "=r"(a) : "l"(p));
    return a;
}
DI void cp_async16(uint32_t dst, const void* src) {
    asm volatile("cp.async.cg.shared.global [%0], [%1], 16;" :: "r"(dst), "l"(src) : "memory");
}
DI void cp_commit() { asm volatile("cp.async.commit_group;" ::: "memory"); }
template <int Nn> DI void cp_wait() { asm volatile("cp.async.wait_group %0;" :: "n"(Nn) : "memory"); }

DI void ldmatrix_x4(uint32_t* r, uint32_t addr) {
    asm volatile("ldmatrix.sync.aligned.m8n8.x4.shared.b16 {%0,%1,%2,%3}, [%4];"
                 : "=r"(r[0]), "=r"(r[1]), "=r"(r[2]), "=r"(r[3]) : "r"(addr));
}
DI void mma16816(float* c, const uint32_t* a, uint32_t b0, uint32_t b1) {
    asm volatile(
        "mma.sync.aligned.m16n8k16.row.col.f32.f16.f16.f32 "
        "{%0,%1,%2,%3}, {%4,%5,%6,%7}, {%8,%9}, {%0,%1,%2,%3};"
        : "+f"(c[0]), "+f"(c[1]), "+f"(c[2]), "+f"(c[3])
        : "r"(a[0]), "r"(a[1]), "r"(a[2]), "r"(a[3]), "r"(b0), "r"(b1));
}
DI uint32_t swz128(uint32_t b) { return b ^ ((b >> 3) & 0x70); }
// 256B-row tile: element chunk c (16B units, 0..15) at row r, swizzled chunk = c ^ (r&7).
DI uint32_t off256(int row, int c) {
    return (uint32_t)(row * 256) + (uint32_t)(((c ^ (row & 7)) << 4));
}

// ============================================================
// k_main — merged prep:
//   blocks [0, 1024)      : W_eff 64x64 tiles (in-CTA fp16 A/B build + MMA fold)
//   blocks [1024, 5120)   : x fp32 -> fp16 (grid-stride, unroll-4 for MLP)
// ============================================================
constexpr int WEFF_BLOCKS2 = 32 * 32;          // 1024 (64x64 tiles over 2048x2048)
constexpr int CONV_BLOCKS2 = 4096;
constexpr int MAIN_BLOCKS = WEFF_BLOCKS2 + CONV_BLOCKS2;
constexpr int MAIN_SMEM = 32768;               // A tile 16KB + B tile 16KB

__global__ void __launch_bounds__(256) k_main(const float* __restrict__ x,
                                              const float* __restrict__ weight,
                                              const float* __restrict__ downs,
                                              const float* __restrict__ ups,
                                              const float* __restrict__ scales) {
    const int tid = threadIdx.x;
    const int bx = blockIdx.x;

    if (bx >= WEFF_BLOCKS2) {
        // ---------------- x conversion (unroll-4) ----------------
        const int cb = bx - WEFF_BLOCKS2;
        const size_t base = (size_t)cb * 256 + tid;
        const size_t stride = (size_t)CONV_BLOCKS2 * 256;   // 1,048,576
        const float4* x4 = (const float4*)x;
        uint2* o4 = (uint2*)g_xh_raw;
        // n4 = 8,388,608 = 8 * stride exactly -> 2 outer iters of 4 batched loads
#pragma unroll
        for (int u = 0; u < 2; u++) {
            const size_t i0 = base + (size_t)u * 4 * stride;
            float4 v0 = x4[i0];
            float4 v1 = x4[i0 + stride];
            float4 v2 = x4[i0 + 2 * stride];
            float4 v3 = x4[i0 + 3 * stride];
            uint2 r0, r1, r2, r3;
            __half2 h;
            h = __floats2half2_rn(v0.x, v0.y); r0.x = *(uint32_t*)&h;
            h = __floats2half2_rn(v0.z, v0.w); r0.y = *(uint32_t*)&h;
            h = __floats2half2_rn(v1.x, v1.y); r1.x = *(uint32_t*)&h;
            h = __floats2half2_rn(v1.z, v1.w); r1.y = *(uint32_t*)&h;
            h = __floats2half2_rn(v2.x, v2.y); r2.x = *(uint32_t*)&h;
            h = __floats2half2_rn(v2.z, v2.w); r2.y = *(uint32_t*)&h;
            h = __floats2half2_rn(v3.x, v3.y); r3.x = *(uint32_t*)&h;
            h = __floats2half2_rn(v3.z, v3.w); r3.y = *(uint32_t*)&h;
            o4[i0] = r0;
            o4[i0 + stride] = r1;
            o4[i0 + 2 * stride] = r2;
            o4[i0 + 3 * stride] = r3;
        }
        return;
    }

    // ---------------- W_eff 64x64 tile ----------------
    // W_eff[o][i] = W[o][i] + sum_k Ah[o][k]*Bh[i][k],
    //   Ah[o][l*32+r] = half(scales[l]*ups[l][o][r]),  Bh[i][k] = half(downs[k][i])
    extern __shared__ char smem[];
    const uint32_t sb = smem_u32(smem);
    const int wid = tid >> 5, lane = tid & 31;
    const int M0 = (bx >> 5) * 64;   // o tile
    const int N0 = (bx & 31) * 64;   // i tile

    // --- build A tile (64 rows x 128 k, fp16, 256B rows, swizzled) ---
    {
        const int l = tid >> 6;      // 0..3
        const int o = tid & 63;      // 0..63
        const float s = scales[l];
        const float4* up = (const float4*)(ups + ((size_t)l * Ndim + (M0 + o)) * Rr);
        float4 v[8];
#pragma unroll
        for (int j = 0; j < 8; j++) v[j] = up[j];
#pragma unroll
        for (int j = 0; j < 4; j++) {
            __half hh[8];
            hh[0] = __float2half_rn(s * v[2 * j].x);
            hh[1] = __float2half_rn(s * v[2 * j].y);
            hh[2] = __float2half_rn(s * v[2 * j].z);
            hh[3] = __float2half_rn(s * v[2 * j].w);
            hh[4] = __float2half_rn(s * v[2 * j + 1].x);
            hh[5] = __float2half_rn(s * v[2 * j + 1].y);
            hh[6] = __float2half_rn(s * v[2 * j + 1].z);
            hh[7] = __float2half_rn(s * v[2 * j + 1].w);
            *(uint4*)(smem + off256(o, l * 4 + j)) = *(uint4*)hh;
        }
    }
    // --- build B tile (64 rows(i) x 128 k): gather 8 k per thread-task ---
#pragma unroll
    for (int it = 0; it < 4; it++) {
        const int task = it * 256 + tid;   // 0..1023
        const int oct = task >> 6;         // k-octet 0..15
        const int i = task & 63;
        __half hh[8];
#pragma unroll
        for (int jj = 0; jj < 8; jj++)
            hh[jj] = __float2half_rn(downs[(size_t)(oct * 8 + jj) * Kdim + N0 + i]);
        *(uint4*)(smem + 16384 + off256(i, oct)) = *(uint4*)hh;
    }
    __syncthreads();

    // --- MMA fold: warp tile 16(m) x 32(n), 8 warps (4x2) ---
    const int warp_m = (wid & 3) * 16;
    const int warp_n = (wid >> 2) * 32;
    float acc[4][4];
#pragma unroll
    for (int nt = 0; nt < 4; nt++)
#pragma unroll
        for (int c = 0; c < 4; c++) acc[nt][c] = 0.f;

    const int lane15 = lane & 15;
    const int laneHi = lane >> 4;
    const int rowA = warp_m + lane15;
    const int rowB0 = warp_n + lane15;
    const int rowB1 = warp_n + 16 + lane15;

#pragma unroll
    for (int ks = 0; ks < 8; ks++) {
        uint32_t a[4], b[2][4];
        ldmatrix_x4(a, sb + off256(rowA, ks * 2 + laneHi));
        ldmatrix_x4(b[0], sb + 16384 + off256(rowB0, ks * 2 + laneHi));
        ldmatrix_x4(b[1], sb + 16384 + off256(rowB1, ks * 2 + laneHi));
#pragma unroll
        for (int nt = 0; nt < 4; nt++) {
            const int np = nt >> 1, half = nt & 1;
            mma16816(acc[nt], a, b[np][half], b[np][2 + half]);
        }
    }

    // --- epilogue: W_eff = acc + W -> fp16 ---
    __half* gw = (__half*)g_wh_raw;
    const int gq = lane >> 2, rq = lane & 3;
#pragma unroll
    for (int nt = 0; nt < 4; nt++) {
        const int m = M0 + warp_m + gq;          // o
        const int n = N0 + warp_n + nt * 8 + rq * 2;   // i
        float2 w0 = *(const float2*)&weight[(size_t)m * Kdim + n];
        float2 w1 = *(const float2*)&weight[(size_t)(m + 8) * Kdim + n];
        __half2 p0 = __floats2half2_rn(acc[nt][0] + w0.x, acc[nt][1] + w0.y);
        __half2 p1 = __floats2half2_rn(acc[nt][2] + w1.x, acc[nt][3] + w1.y);
        *(uint32_t*)&gw[(size_t)m * Kdim + n] = *(uint32_t*)&p0;
        *(uint32_t*)&gw[(size_t)(m + 8) * Kdim + n] = *(uint32_t*)&p1;
    }
}

// ============================================================
// Main GEMM (exact R2 structure — best measured, UNCHANGED):
//   mma.sync.m16n8k16 fp32 acc, BM=BN=128, BK=64, 3-stage cp.async,
//   256 threads (8 warps 2x4, warp tile 64x32), 2 CTAs/SM.
// ============================================================
constexpr int BK = 64;
constexpr int STAGES = 3;
constexpr int NK = Kdim / BK;                    // 32
constexpr int AB_BYTES = 128 * 128;              // 16 KB
constexpr int STG_BYTES = 2 * AB_BYTES;          // 32 KB
constexpr int GEMM_SMEM = STAGES * STG_BYTES;    // 96 KB

__global__ void __launch_bounds__(256, 2) k_gemm(const float* __restrict__ bias,
                                                 float* __restrict__ out) {
    extern __shared__ char smem[];
    const uint32_t sb = smem_u32(smem);
    const int tid = threadIdx.x;
    const int wid = tid >> 5, lane = tid & 31;
    const int M0 = blockIdx.y * 128, N0 = blockIdx.x * 128;

    const int warp_m = (wid & 1) * 64;
    const int warp_n = (wid >> 1) * 32;

    const __half* gA = (const __half*)g_xh_raw;
    const __half* gB = (const __half*)g_wh_raw;

    auto load_stage = [&](int s, int kk) {
        const uint32_t base = sb + s * STG_BYTES;
        const int k0 = kk * BK;
#pragma unroll
        for (int it = 0; it < 4; it++) {
            int c = tid + it * 256;
            int row = c >> 3, col = c & 7;
            cp_async16(base + swz128(row * 128 + col * 16),
                       gA + (size_t)(M0 + row) * Kdim + k0 + col * 8);
        }
#pragma unroll
        for (int it = 0; it < 4; it++) {
            int c = tid + it * 256;
            int row = c >> 3, col = c & 7;
            cp_async16(base + AB_BYTES + swz128(row * 128 + col * 16),
                       gB + (size_t)(N0 + row) * Kdim + k0 + col * 8);
        }
    };

    float acc[4][4][4];
#pragma unroll
    for (int mt = 0; mt < 4; mt++)
#pragma unroll
        for (int nt = 0; nt < 4; nt++)
#pragma unroll
            for (int c = 0; c < 4; c++) acc[mt][nt][c] = 0.f;

    load_stage(0, 0); cp_commit();
    load_stage(1, 1); cp_commit();

    const int lane15 = lane & 15;
    const int laneHi = lane >> 4;

    for (int k = 0; k < NK; k++) {
        cp_wait<STAGES - 2>();
        __syncthreads();

        const int kn = k + STAGES - 1;
        if (kn < NK) load_stage(kn % STAGES, kn);
        cp_commit();

        const int s = k % STAGES;
        const uint32_t Ab = sb + s * STG_BYTES;
        const uint32_t Bb = Ab + AB_BYTES;

#pragma unroll
        for (int ks = 0; ks < 4; ks++) {
            uint32_t a[4][4], b[2][4];
#pragma unroll
            for (int mt = 0; mt < 4; mt++) {
                int row = warp_m + mt * 16 + lane15;
                ldmatrix_x4(a[mt], Ab + swz128(row * 128 + (ks * 2 + laneHi) * 16));
            }
#pragma unroll
            for (int np = 0; np < 2; np++) {
                int row = warp_n + np * 16 + lane15;
                ldmatrix_x4(b[np], Bb + swz128(row * 128 + (ks * 2 + laneHi) * 16));
            }
#pragma unroll
            for (int mt = 0; mt < 4; mt++)
#pragma unroll
                for (int nt = 0; nt < 4; nt++) {
                    const int np = nt >> 1, half = nt & 1;
                    mma16816(acc[mt][nt], a[mt], b[np][half], b[np][2 + half]);
                }
        }
    }

    const int gq = lane >> 2, rq = lane & 3;
#pragma unroll
    for (int mt = 0; mt < 4; mt++) {
#pragma unroll
        for (int nt = 0; nt < 4; nt++) {
            int m = M0 + warp_m + mt * 16 + gq;
            int n = N0 + warp_n + nt * 8 + rq * 2;
            float2 bv = *(const float2*)&bias[n];
            float2 v0, v1;
            v0.x = acc[mt][nt][0] + bv.x;
            v0.y = acc[mt][nt][1] + bv.y;
            v1.x = acc[mt][nt][2] + bv.x;
            v1.y = acc[mt][nt][3] + bv.y;
            *(float2*)&out[(size_t)m * Ndim + n] = v0;
            *(float2*)&out[(size_t)(m + 8) * Ndim + n] = v1;
        }
    }
}

// ============================================================
// launch
// ============================================================
extern "C" void kernel_launch(void* const* d_in, const int* in_sizes, int n_in,
                              void* d_out, int out_size) {
    const float* x      = (const float*)d_in[0];
    const float* weight = (const float*)d_in[1];
    const float* bias   = (const float*)d_in[2];
    const float* downs  = (const float*)d_in[3];
    const float* ups    = (const float*)d_in[4];
    const float* scales = (const float*)d_in[5];
    float* out = (float*)d_out;

    cudaFuncSetAttribute(k_gemm, cudaFuncAttributeMaxDynamicSharedMemorySize, GEMM_SMEM);

    k_main<<<MAIN_BLOCKS, 256, MAIN_SMEM>>>(x, weight, downs, ups, scales);
    k_gemm<<<dim3(Ndim / 128, Mdim / 128), 256, GEMM_SMEM>>>(bias, out);
}

// round 16
// speedup vs baseline: 1.5093x; 1.5093x over previous
#include <cuda_runtime.h>
#include <cuda_fp16.h>
#include <cstdint>

#define DI __device__ __forceinline__

// ---------------- problem dims ----------------
constexpr int Mdim = 16384;   // B*S
constexpr int Kdim = 2048;    // IN
constexpr int Ndim = 2048;    // OUT
constexpr int LR   = 128;     // L*R
constexpr int Rr   = 32;

// ---------------- scratch ----------------
__device__ uint4 g_xh_raw[(size_t)Mdim * Kdim * 2 / 16];   // fp16 x      (64 MB)
__device__ uint4 g_wh_raw[(size_t)Ndim * Kdim * 2 / 16];   // fp16 W_eff  (8 MB)
__device__ uint4 g_ah_raw[(size_t)Ndim * LR * 2 / 16];     // fp16 scaled ups^T [o][k]
__device__ uint4 g_bh_raw[(size_t)Kdim * LR * 2 / 16];     // fp16 downs^T [i][k]

// ---------------- PTX helpers (family-portable only) ----------------
DI uint32_t smem_u32(const void* p) {
    uint32_t a;
    asm("{ .reg .u64 t; cvta.to.shared.u64 t, %1; cvt.u32.u64 %0, t; }" : "=r"(a) : "l"(p));
    return a;
}
DI void cp_async16(uint32_t dst, const void* src) {
    asm volatile("cp.async.cg.shared.global [%0], [%1], 16;" :: "r"(dst), "l"(src) : "memory");
}
DI void cp_commit() { asm volatile("cp.async.commit_group;" ::: "memory"); }
template <int Nn> DI void cp_wait() { asm volatile("cp.async.wait_group %0;" :: "n"(Nn) : "memory"); }

DI void ldmatrix_x4(uint32_t* r, uint32_t addr) {
    asm volatile("ldmatrix.sync.aligned.m8n8.x4.shared.b16 {%0,%1,%2,%3}, [%4];"
                 : "=r"(r[0]), "=r"(r[1]), "=r"(r[2]), "=r"(r[3]) : "r"(addr));
}
DI void mma16816(float* c, const uint32_t* a, uint32_t b0, uint32_t b1) {
    asm volatile(
        "mma.sync.aligned.m16n8k16.row.col.f32.f16.f16.f32 "
        "{%0,%1,%2,%3}, {%4,%5,%6,%7}, {%8,%9}, {%0,%1,%2,%3};"
        : "+f"(c[0]), "+f"(c[1]), "+f"(c[2]), "+f"(c[3])
        : "r"(a[0]), "r"(a[1]), "r"(a[2]), "r"(a[3]), "r"(b0), "r"(b1));
}
DI uint32_t swz128(uint32_t b) { return b ^ ((b >> 3) & 0x70); }

// ============================================================
// k_build — tiny: build fp16 fold operands (runs before weff_mma)
//   blocks [0, 128)    : Ah[o][l*32+r] = half(scales[l] * ups[l][o][r])
//   blocks [128, 192)  : Bh[i][k] = half(downs[k][i])
// ============================================================
constexpr int ABUILD_BLOCKS = 128;
constexpr int BBUILD_BLOCKS = 64;

__global__ void __launch_bounds__(256) k_build(const float* __restrict__ downs,
                                               const float* __restrict__ ups,
                                               const float* __restrict__ scales) {
    const int tid = threadIdx.x;
    const int bx = blockIdx.x;

    if (bx < ABUILD_BLOCKS) {
        int t = bx * 256 + tid;   // 0 .. 2048*16-1
        int o = t >> 4;
        int q = t & 15;
        int l = q >> 2;
        int r0 = (q & 3) * 8;
        float s = scales[l];
        const float* up = ups + ((size_t)l * Ndim + o) * Rr + r0;
        float4 v0 = *(const float4*)(up);
        float4 v1 = *(const float4*)(up + 4);
        __half h[8];
        h[0] = __float2half_rn(s * v0.x); h[1] = __float2half_rn(s * v0.y);
        h[2] = __float2half_rn(s * v0.z); h[3] = __float2half_rn(s * v0.w);
        h[4] = __float2half_rn(s * v1.x); h[5] = __float2half_rn(s * v1.y);
        h[6] = __float2half_rn(s * v1.z); h[7] = __float2half_rn(s * v1.w);
        __half* A = (__half*)g_ah_raw;
        *(uint4*)&A[(size_t)o * LR + l * Rr + r0] = *(uint4*)h;
        return;
    }

    int t = (bx - ABUILD_BLOCKS) * 256 + tid;   // 0 .. 2048*8-1
    int i = t >> 3;
    int k0 = (t & 7) * 16;
    __half h[16];
#pragma unroll
    for (int j = 0; j < 16; j++)
        h[j] = __float2half_rn(downs[(size_t)(k0 + j) * Kdim + i]);
    __half* B = (__half*)g_bh_raw;
    uint4* dst = (uint4*)&B[(size_t)i * LR + k0];
    dst[0] = ((uint4*)h)[0];
    dst[1] = ((uint4*)h)[1];
}

// ============================================================
// k_convert — x fp32 -> fp16 (overlapped stream; DRAM-bound)
// ============================================================
__global__ void __launch_bounds__(256) k_convert(const float* __restrict__ x) {
    size_t i = (size_t)blockIdx.x * 256 + threadIdx.x;
    const size_t stride = (size_t)gridDim.x * 256;
    const float4* x4 = (const float4*)x;
    uint2* o4 = (uint2*)g_xh_raw;
    const size_t n4 = (size_t)Mdim * Kdim / 4;
    for (; i < n4; i += stride) {
        float4 v = x4[i];
        __half2 a = __floats2half2_rn(v.x, v.y);
        __half2 b = __floats2half2_rn(v.z, v.w);
        uint2 u;
        u.x = *(uint32_t*)&a;
        u.y = *(uint32_t*)&b;
        o4[i] = u;
    }
}

// ============================================================
// k_weff_mma: W_eff[o][i] = W[o][i] + sum_k Ah[o][k]*Bh[i][k]  (verbatim R14)
// ============================================================
constexpr int WF_AB = 128 * 128;
constexpr int WF_STG = 2 * WF_AB;
constexpr int WF_SMEM = 2 * WF_STG;       // 64 KB

__global__ void __launch_bounds__(256, 2) k_weff_mma(const float* __restrict__ weight) {
    extern __shared__ char smem[];
    const uint32_t sb = smem_u32(smem);
    const int tid = threadIdx.x;
    const int wid = tid >> 5, lane = tid & 31;
    const int M0 = blockIdx.y * 128, N0 = blockIdx.x * 128;

    const int warp_m = (wid & 1) * 64;
    const int warp_n = (wid >> 1) * 32;

    const __half* gA = (const __half*)g_ah_raw;
    const __half* gB = (const __half*)g_bh_raw;

#pragma unroll
    for (int s = 0; s < 2; s++) {
        const uint32_t base = sb + s * WF_STG;
        const int k0 = s * 64;
#pragma unroll
        for (int it = 0; it < 4; it++) {
            int c = tid + it * 256;
            int row = c >> 3, col = c & 7;
            cp_async16(base + swz128(row * 128 + col * 16),
                       gA + (size_t)(M0 + row) * LR + k0 + col * 8);
        }
#pragma unroll
        for (int it = 0; it < 4; it++) {
            int c = tid + it * 256;
            int row = c >> 3, col = c & 7;
            cp_async16(base + WF_AB + swz128(row * 128 + col * 16),
                       gB + (size_t)(N0 + row) * LR + k0 + col * 8);
        }
    }
    cp_commit();
    cp_wait<0>();
    __syncthreads();

    float acc[4][4][4];
#pragma unroll
    for (int mt = 0; mt < 4; mt++)
#pragma unroll
        for (int nt = 0; nt < 4; nt++)
#pragma unroll
            for (int c = 0; c < 4; c++) acc[mt][nt][c] = 0.f;

    const int lane15 = lane & 15;
    const int laneHi = lane >> 4;

#pragma unroll
    for (int s = 0; s < 2; s++) {
        const uint32_t Ab = sb + s * WF_STG;
        const uint32_t Bb = Ab + WF_AB;
#pragma unroll
        for (int ks = 0; ks < 4; ks++) {
            uint32_t a[4][4], b[2][4];
#pragma unroll
            for (int mt = 0; mt < 4; mt++) {
                int row = warp_m + mt * 16 + lane15;
                ldmatrix_x4(a[mt], Ab + swz128(row * 128 + (ks * 2 + laneHi) * 16));
            }
#pragma unroll
            for (int np = 0; np < 2; np++) {
                int row = warp_n + np * 16 + lane15;
                ldmatrix_x4(b[np], Bb + swz128(row * 128 + (ks * 2 + laneHi) * 16));
            }
#pragma unroll
            for (int mt = 0; mt < 4; mt++)
#pragma unroll
                for (int nt = 0; nt < 4; nt++) {
                    const int np = nt >> 1, half = nt & 1;
                    mma16816(acc[mt][nt], a[mt], b[np][half], b[np][2 + half]);
                }
        }
    }

    __half* gw = (__half*)g_wh_raw;
    const int gq = lane >> 2, rq = lane & 3;
#pragma unroll
    for (int mt = 0; mt < 4; mt++) {
#pragma unroll
        for (int nt = 0; nt < 4; nt++) {
            int m = M0 + warp_m + mt * 16 + gq;
            int n = N0 + warp_n + nt * 8 + rq * 2;
            float2 w0 = *(const float2*)&weight[(size_t)m * Kdim + n];
            float2 w1 = *(const float2*)&weight[(size_t)(m + 8) * Kdim + n];
            __half2 p0 = __floats2half2_rn(acc[mt][nt][0] + w0.x, acc[mt][nt][1] + w0.y);
            __half2 p1 = __floats2half2_rn(acc[mt][nt][2] + w1.x, acc[mt][nt][3] + w1.y);
            *(uint32_t*)&gw[(size_t)m * Kdim + n] = *(uint32_t*)&p0;
            *(uint32_t*)&gw[(size_t)(m + 8) * Kdim + n] = *(uint32_t*)&p1;
        }
    }
}

// ============================================================
// Main GEMM (exact R2/R14 structure — best measured, UNCHANGED)
// ============================================================
constexpr int BK = 64;
constexpr int STAGES = 3;
constexpr int NK = Kdim / BK;
constexpr int AB_BYTES = 128 * 128;
constexpr int STG_BYTES = 2 * AB_BYTES;
constexpr int GEMM_SMEM = STAGES * STG_BYTES;    // 96 KB

__global__ void __launch_bounds__(256, 2) k_gemm(const float* __restrict__ bias,
                                                 float* __restrict__ out) {
    extern __shared__ char smem[];
    const uint32_t sb = smem_u32(smem);
    const int tid = threadIdx.x;
    const int wid = tid >> 5, lane = tid & 31;
    const int M0 = blockIdx.y * 128, N0 = blockIdx.x * 128;

    const int warp_m = (wid & 1) * 64;
    const int warp_n = (wid >> 1) * 32;

    const __half* gA = (const __half*)g_xh_raw;
    const __half* gB = (const __half*)g_wh_raw;

    auto load_stage = [&](int s, int kk) {
        const uint32_t base = sb + s * STG_BYTES;
        const int k0 = kk * BK;
#pragma unroll
        for (int it = 0; it < 4; it++) {
            int c = tid + it * 256;
            int row = c >> 3, col = c & 7;
            cp_async16(base + swz128(row * 128 + col * 16),
                       gA + (size_t)(M0 + row) * Kdim + k0 + col * 8);
        }
#pragma unroll
        for (int it = 0; it < 4; it++) {
            int c = tid + it * 256;
            int row = c >> 3, col = c & 7;
            cp_async16(base + AB_BYTES + swz128(row * 128 + col * 16),
                       gB + (size_t)(N0 + row) * Kdim + k0 + col * 8);
        }
    };

    float acc[4][4][4];
#pragma unroll
    for (int mt = 0; mt < 4; mt++)
#pragma unroll
        for (int nt = 0; nt < 4; nt++)
#pragma unroll
            for (int c = 0; c < 4; c++) acc[mt][nt][c] = 0.f;

    load_stage(0, 0); cp_commit();
    load_stage(1, 1); cp_commit();

    const int lane15 = lane & 15;
    const int laneHi = lane >> 4;

    for (int k = 0; k < NK; k++) {
        cp_wait<STAGES - 2>();
        __syncthreads();

        const int kn = k + STAGES - 1;
        if (kn < NK) load_stage(kn % STAGES, kn);
        cp_commit();

        const int s = k % STAGES;
        const uint32_t Ab = sb + s * STG_BYTES;
        const uint32_t Bb = Ab + AB_BYTES;

#pragma unroll
        for (int ks = 0; ks < 4; ks++) {
            uint32_t a[4][4], b[2][4];
#pragma unroll
            for (int mt = 0; mt < 4; mt++) {
                int row = warp_m + mt * 16 + lane15;
                ldmatrix_x4(a[mt], Ab + swz128(row * 128 + (ks * 2 + laneHi) * 16));
            }
#pragma unroll
            for (int np = 0; np < 2; np++) {
                int row = warp_n + np * 16 + lane15;
                ldmatrix_x4(b[np], Bb + swz128(row * 128 + (ks * 2 + laneHi) * 16));
            }
#pragma unroll
            for (int mt = 0; mt < 4; mt++)
#pragma unroll
                for (int nt = 0; nt < 4; nt++) {
                    const int np = nt >> 1, half = nt & 1;
                    mma16816(acc[mt][nt], a[mt], b[np][half], b[np][2 + half]);
                }
        }
    }

    const int gq = lane >> 2, rq = lane & 3;
#pragma unroll
    for (int mt = 0; mt < 4; mt++) {
#pragma unroll
        for (int nt = 0; nt < 4; nt++) {
            int m = M0 + warp_m + mt * 16 + gq;
            int n = N0 + warp_n + nt * 8 + rq * 2;
            float2 bv = *(const float2*)&bias[n];
            float2 v0, v1;
            v0.x = acc[mt][nt][0] + bv.x;
            v0.y = acc[mt][nt][1] + bv.y;
            v1.x = acc[mt][nt][2] + bv.x;
            v1.y = acc[mt][nt][3] + bv.y;
            *(float2*)&out[(size_t)m * Ndim + n] = v0;
            *(float2*)&out[(size_t)(m + 8) * Ndim + n] = v1;
        }
    }
}

// ============================================================
// launch — stream-forked: convert (DRAM-bound) overlaps
// build->weff_mma (tensor/L2-bound); join before gemm.
// Streams/events are host objects created per call (kernel_launch
// runs only for correctness + capture; replays use the graph).
// ============================================================
extern "C" void kernel_launch(void* const* d_in, const int* in_sizes, int n_in,
                              void* d_out, int out_size) {
    const float* x      = (const float*)d_in[0];
    const float* weight = (const float*)d_in[1];
    const float* bias   = (const float*)d_in[2];
    const float* downs  = (const float*)d_in[3];
    const float* ups    = (const float*)d_in[4];
    const float* scales = (const float*)d_in[5];
    float* out = (float*)d_out;

    cudaFuncSetAttribute(k_gemm, cudaFuncAttributeMaxDynamicSharedMemorySize, GEMM_SMEM);
    cudaFuncSetAttribute(k_weff_mma, cudaFuncAttributeMaxDynamicSharedMemorySize, WF_SMEM);

    cudaStream_t s2;
    cudaEvent_t evFork, evJoin;
    cudaStreamCreateWithFlags(&s2, cudaStreamNonBlocking);
    cudaEventCreateWithFlags(&evFork, cudaEventDisableTiming);
    cudaEventCreateWithFlags(&evJoin, cudaEventDisableTiming);

    // fork: convert runs on s2 concurrently with build->weff on stream 0
    cudaEventRecord(evFork, 0);
    cudaStreamWaitEvent(s2, evFork, 0);
    k_convert<<<8192, 256, 0, s2>>>(x);

    k_build<<<ABUILD_BLOCKS + BBUILD_BLOCKS, 256>>>(downs, ups, scales);
    k_weff_mma<<<dim3(Kdim / 128, Ndim / 128), 256, WF_SMEM>>>(weight);

    // join: gemm needs both g_xh (s2) and g_wh (stream 0)
    cudaEventRecord(evJoin, s2);
    cudaStreamWaitEvent(0, evJoin, 0);

    k_gemm<<<dim3(Ndim / 128, Mdim / 128), 256, GEMM_SMEM>>>(bias, out);
}